// round 2
// baseline (speedup 1.0000x reference)
#include <cuda_runtime.h>

#define NMAX  25008
#define FDIM  224
#define NORD  15
#define DV    56
#define TE    128
#define RBP   132   // padded row for rbfT

__device__ float g_q[NMAX * FDIM];
__device__ float g_k[NMAX * FDIM];
__device__ float g_v[NMAX * FDIM];

__device__ __forceinline__ float silu_f(float x) {
    return x / (1.0f + __expf(-x));
}

__global__ void zero_kernel(float* out, int n) {
    int i = blockIdx.x * blockDim.x + threadIdx.x;
    if (i < n) out[i] = 0.0f;
}

// Node precompute: q = silu(Wq@xH), k = silu(Wk@xH), v = Wv@xh
// One thread per output channel c (224). Weight rows live in registers,
// x row staged in smem (warp-uniform broadcast reads).
__global__ __launch_bounds__(224) void node_kernel(
    const float* __restrict__ x, const float* __restrict__ Wq,
    const float* __restrict__ Wk, const float* __restrict__ Wv, int N)
{
    __shared__ float xs[FDIM];
    const int c  = threadIdx.x;
    const int h  = c >> 5;          // head for q/k (DQK=32)
    const int i  = c & 31;
    const int h2 = c / DV;          // head for v (DV=56)
    const int i2 = c - h2 * DV;

    float4 wq[8], wk[8], wv[14];
    const float4* q4 = (const float4*)(Wq + (h * 32 + i) * 32);
    const float4* k4 = (const float4*)(Wk + (h * 32 + i) * 32);
    const float4* v4 = (const float4*)(Wv + (h2 * DV + i2) * DV);
#pragma unroll
    for (int m = 0; m < 8; m++) { wq[m] = q4[m]; wk[m] = k4[m]; }
#pragma unroll
    for (int m = 0; m < 14; m++) wv[m] = v4[m];

    for (int n = blockIdx.x; n < N; n += gridDim.x) {
        __syncthreads();
        xs[c] = x[(size_t)n * FDIM + c];
        __syncthreads();
        float aq = 0.f, ak = 0.f, av = 0.f;
        const float4* xb = (const float4*)(xs + h * 32);
#pragma unroll
        for (int m = 0; m < 8; m++) {
            float4 xv = xb[m];
            aq += wq[m].x * xv.x + wq[m].y * xv.y + wq[m].z * xv.z + wq[m].w * xv.w;
            ak += wk[m].x * xv.x + wk[m].y * xv.y + wk[m].z * xv.z + wk[m].w * xv.w;
        }
        const float4* xb2 = (const float4*)(xs + h2 * DV);
#pragma unroll
        for (int m = 0; m < 14; m++) {
            float4 xv = xb2[m];
            av += wv[m].x * xv.x + wv[m].y * xv.y + wv[m].z * xv.z + wv[m].w * xv.w;
        }
        g_q[(size_t)n * FDIM + c] = silu_f(aq);
        g_k[(size_t)n * FDIM + c] = silu_f(ak);
        g_v[(size_t)n * FDIM + c] = av;
    }
}

// Fused edge kernel: one block per 128 edges.
// smem layout (floats):
//  hT    [224][128]  28672   (layer-1 activations; reused as wT after GEMM2)
//  rbfT  [ 32][132]   4224
//  w2t   [ 16][224]   3584   (streamed W2 chunk)
//  w1r_s [32*112]     3584
//  w1s_s [3*112]       336
//  b1r_s 112, b1s_s 112, b2c_s 224
//  ylm_s [128][15]    1920
//  l0_s  [3][128]      384
//  alp_s [7][128]      896
//  cut_s 128, ii_s 128(int), jj_s 128(int)
__global__ __launch_bounds__(256, 1) void edge_kernel(
    const float* __restrict__ rbf,  const float* __restrict__ ylm,
    const float* __restrict__ cut,  const int* __restrict__ idx_i,
    const int* __restrict__ idx_j,  const float* __restrict__ ev,
    const float* __restrict__ W1r,  const float* __restrict__ b1r,
    const float* __restrict__ W2r,  const float* __restrict__ b2r,
    const float* __restrict__ W1s,  const float* __restrict__ b1s,
    const float* __restrict__ W2s,  const float* __restrict__ b2s,
    float* __restrict__ outx, float* __restrict__ outev,
    int P, int N)
{
    extern __shared__ float sm[];
    float* hT    = sm;               // 28672
    float* rbfT  = hT + 28672;       // 4224
    float* w2t   = rbfT + 4224;      // 3584
    float* w1r_s = w2t + 3584;       // 3584
    float* w1s_s = w1r_s + 3584;     // 336
    float* b1r_s = w1s_s + 336;      // 112
    float* b1s_s = b1r_s + 112;      // 112
    float* b2c_s = b1s_s + 112;      // 224
    float* ylm_s = b2c_s + 224;      // 1920
    float* l0_s  = ylm_s + 1920;     // 384
    float* alp_s = l0_s + 384;       // 896
    float* cut_s = alp_s + 896;      // 128
    int*   ii_s  = (int*)(cut_s + 128);  // 128
    int*   jj_s  = ii_s + 128;           // 128

    const int t  = threadIdx.x;
    const int e0 = blockIdx.x * TE;
    const int nE = min(TE, P - e0);

    // ---- stage 0: loads ----
    if (t < TE) {
        int eg = min(e0 + t, P - 1);
        ii_s[t] = idx_i[eg];
        jj_s[t] = idx_j[eg];
        cut_s[t] = (e0 + t < P) ? cut[e0 + t] : 0.f;
    }
    for (int id = t; id < 3584; id += 256) w1r_s[id] = W1r[id];
    for (int id = t; id < 336;  id += 256) w1s_s[id] = W1s[id];
    if (t < 112) { b1r_s[t] = b1r[t]; b1s_s[t] = b1s[t]; }
    if (t < 224) b2c_s[t] = b2r[t] + b2s[t];
    for (int id = t; id < TE * NORD; id += 256) {
        ylm_s[id] = (e0 + id / NORD < P) ? ylm[(size_t)e0 * NORD + id] : 0.f;
    }
    for (int id = t; id < TE * 32; id += 256) {
        int e = id >> 5, j = id & 31;
        rbfT[j * RBP + e] = (e0 + e < P) ? rbf[(size_t)(e0 + e) * 32 + j] : 0.f;
    }
    __syncthreads();

    // scale rbf by cut; compute l0 contraction
    for (int id = t; id < TE * 32; id += 256) {
        int j = id >> 7, e = id & 127;
        rbfT[j * RBP + e] *= cut_s[e];
    }
    if (t < TE) {
        int a = ii_s[t] * NORD, b = jj_s[t] * NORD;
        float s0 = 0.f, s1 = 0.f, s2 = 0.f;
#pragma unroll
        for (int o = 0; o < NORD; o++) {
            float d = ev[b + o] - ev[a + o];
            float dd = d * d;
            if (o < 3) s0 += dd; else if (o < 8) s1 += dd; else s2 += dd;
        }
        l0_s[t] = s0; l0_s[128 + t] = s1; l0_s[256 + t] = s2;
    }
    __syncthreads();

    // ---- GEMM1: hT[c][e] = silu(layer1) ----
    for (int id = t; id < 224 * TE; id += 256) {
        int c = id >> 7, e = id & 127;
        float acc;
        if (c < 112) {
            acc = b1r_s[c];
#pragma unroll
            for (int j = 0; j < 32; j++) acc += rbfT[j * RBP + e] * w1r_s[j * 112 + c];
        } else {
            int c2 = c - 112;
            acc = b1s_s[c2] + l0_s[e] * w1s_s[c2]
                            + l0_s[128 + e] * w1s_s[112 + c2]
                            + l0_s[256 + e] * w1s_s[224 + c2];
        }
        hT[c * TE + e] = silu_f(acc);
    }
    __syncthreads();

    // ---- GEMM2: w[128][224] = h[128][224] @ W2cat[224][224], reg tile 4x28 ----
    const int tx = t & 31, ty = t >> 5;
    const int ce0 = 4 * tx;    // edge base
    const int cc0 = 28 * ty;   // col base
    float acc[4][28];
#pragma unroll
    for (int i = 0; i < 4; i++)
#pragma unroll
        for (int j = 0; j < 28; j++) acc[i][j] = 0.f;

    for (int kc = 0; kc < 14; kc++) {
        __syncthreads();
#pragma unroll
        for (int it = 0; it < 14; it++) {
            int id = t + 256 * it;
            int kk = id / 224, cc = id - kk * 224;
            int k = kc * 16 + kk;
            const float* src = (k < 112) ? (W2r + k * 224) : (W2s + (k - 112) * 224);
            w2t[id] = src[cc];
        }
        __syncthreads();
#pragma unroll
        for (int kk = 0; kk < 16; kk++) {
            float4 av = *(const float4*)(hT + (kc * 16 + kk) * TE + ce0);
            const float4* brow = (const float4*)(w2t + kk * 224 + cc0);
#pragma unroll
            for (int m = 0; m < 7; m++) {
                float4 bv = brow[m];
                acc[0][4*m+0] += av.x * bv.x; acc[0][4*m+1] += av.x * bv.y;
                acc[0][4*m+2] += av.x * bv.z; acc[0][4*m+3] += av.x * bv.w;
                acc[1][4*m+0] += av.y * bv.x; acc[1][4*m+1] += av.y * bv.y;
                acc[1][4*m+2] += av.y * bv.z; acc[1][4*m+3] += av.y * bv.w;
                acc[2][4*m+0] += av.z * bv.x; acc[2][4*m+1] += av.z * bv.y;
                acc[2][4*m+2] += av.z * bv.z; acc[2][4*m+3] += av.z * bv.w;
                acc[3][4*m+0] += av.w * bv.x; acc[3][4*m+1] += av.w * bv.y;
                acc[3][4*m+2] += av.w * bv.z; acc[3][4*m+3] += av.w * bv.w;
            }
        }
    }
    __syncthreads();   // all hT reads done before overlay write

    // write w (+bias) transposed into hT region: wT[c][e]
#pragma unroll
    for (int j = 0; j < 28; j++) {
        float bb = b2c_s[cc0 + j];
        float4 wv = make_float4(acc[0][j] + bb, acc[1][j] + bb,
                                acc[2][j] + bb, acc[3][j] + bb);
        *(float4*)(hT + (cc0 + j) * TE + ce0) = wv;
    }
    __syncthreads();

    // ---- stage 3: alpha[hh][e] = cut * sum_j q_i*w*k_j ----
    for (int it = 0; it < 4; it++) {
        int task = t + 256 * it;
        if (task < 7 * TE) {
            int hh = task >> 7, e = task & 127;
            int ni = ii_s[e], nj = jj_s[e];
            const float4* qv = (const float4*)(g_q + (size_t)ni * FDIM + hh * 32);
            const float4* kv = (const float4*)(g_k + (size_t)nj * FDIM + hh * 32);
            float s = 0.f;
#pragma unroll
            for (int m = 0; m < 8; m++) {
                float4 q4 = qv[m], k4 = kv[m];
                int wb = (hh * 32 + 4 * m) * TE + e;
                s += q4.x * k4.x * hT[wb];
                s += q4.y * k4.y * hT[wb + TE];
                s += q4.z * k4.z * hT[wb + 2 * TE];
                s += q4.w * k4.w * hT[wb + 3 * TE];
            }
            alp_s[hh * TE + e] = s * cut_s[e];
        }
    }
    __syncthreads();

    // ---- stage 4: segmented scatter (idx_i sorted; atomics at flush) ----
    if (t < FDIM) {
        int hc = t / DV;
        const float* arow = alp_s + hc * TE;
        int icur = ii_s[0];
        float a2 = 0.f;
        for (int e = 0; e < nE; e++) {
            int ie = ii_s[e];
            if (ie != icur) {
                atomicAdd(outx + (size_t)icur * FDIM + t, a2);
                a2 = 0.f; icur = ie;
            }
            a2 += arow[e] * g_v[(size_t)jj_s[e] * FDIM + t];
        }
        atomicAdd(outx + (size_t)icur * FDIM + t, a2);
    } else if (t < FDIM + NORD) {
        int o = t - FDIM;
        int hd = (o < 3) ? 4 : (o < 8) ? 5 : 6;
        const float* arow = alp_s + hd * TE;
        int icur = ii_s[0];
        float a2 = 0.f;
        for (int e = 0; e < nE; e++) {
            int ie = ii_s[e];
            if (ie != icur) {
                atomicAdd(outev + (size_t)icur * NORD + o, a2);
                a2 = 0.f; icur = ie;
            }
            a2 += arow[e] * ylm_s[e * NORD + o];
        }
        atomicAdd(outev + (size_t)icur * NORD + o, a2);
    }
}

extern "C" void kernel_launch(void* const* d_in, const int* in_sizes, int n_in,
                              void* d_out, int out_size)
{
    const float* x    = (const float*)d_in[0];
    const float* ev   = (const float*)d_in[1];
    const float* rbf  = (const float*)d_in[2];
    const float* ylm  = (const float*)d_in[3];
    const float* cutp = (const float*)d_in[4];
    const int*   idxi = (const int*)d_in[5];
    const int*   idxj = (const int*)d_in[6];
    const float* W1r  = (const float*)d_in[7];
    const float* b1r  = (const float*)d_in[8];
    const float* W2r  = (const float*)d_in[9];
    const float* b2r  = (const float*)d_in[10];
    const float* W1s  = (const float*)d_in[11];
    const float* b1s  = (const float*)d_in[12];
    const float* W2s  = (const float*)d_in[13];
    const float* b2s  = (const float*)d_in[14];
    const float* Wq   = (const float*)d_in[15];
    const float* Wk   = (const float*)d_in[16];
    const float* Wv   = (const float*)d_in[17];

    int N = in_sizes[0] / FDIM;
    int P = in_sizes[4];
    float* out   = (float*)d_out;
    float* outx  = out;
    float* outev = out + (size_t)N * FDIM;

    zero_kernel<<<(out_size + 255) / 256, 256>>>(out, out_size);
    node_kernel<<<1024, 224>>>(x, Wq, Wk, Wv, N);

    const int smem_bytes = (28672 + 4224 + 3584 + 3584 + 336 + 112 + 112 + 224 +
                            1920 + 384 + 896 + 128 + 256) * 4;  // 177,728 B
    cudaFuncSetAttribute(edge_kernel,
                         cudaFuncAttributeMaxDynamicSharedMemorySize, smem_bytes);
    int nb = (P + TE - 1) / TE;
    edge_kernel<<<nb, 256, smem_bytes>>>(rbf, ylm, cutp, idxi, idxj, ev,
                                         W1r, b1r, W2r, b2r, W1s, b1s, W2s, b2s,
                                         outx, outev, P, N);
}

// round 5
// speedup vs baseline: 1.7131x; 1.7131x over previous
#include <cuda_runtime.h>
#include <cuda_bf16.h>

#define FDIM 224
#define NORD 15
#define NMAX 25008
#define PMAX 400128
#define TE   128

__device__ float g_q[NMAX * FDIM];
__device__ float g_k[NMAX * FDIM];
__device__ float g_v[NMAX * FDIM];
__device__ __nv_bfloat16 g_B2[224 * 512];
__device__ float g_alpha[(size_t)PMAX * 8];

// smem byte offsets
#define OFF_CUT   0
#define OFF_B2C   512
#define OFF_II    1408
#define OFF_JJ    1920
#define OFF_L0    2432
#define OFF_A2H   4096
#define OFF_A2L   63488
#define OFF_PANEL 122880
#define PANEL_SZ  21504
#define OFF_A1H   122880
#define OFF_A1L   137216
#define OFF_B1H   4096
#define OFF_B1L   29184
#define OFF_QK    4096
#define SM_TOTAL  165888

__device__ __forceinline__ unsigned smem_u32(const void* p) {
    unsigned a;
    asm("{ .reg .u64 t; cvta.to.shared.u64 t, %1; cvt.u32.u64 %0, t; }" : "=r"(a) : "l"(p));
    return a;
}
__device__ __forceinline__ float silu_f(float x) {
    return __fdividef(x, 1.0f + __expf(-x));
}
__device__ __forceinline__ void ldm4(unsigned* r, unsigned addr) {
    asm volatile("ldmatrix.sync.aligned.m8n8.x4.shared.b16 {%0,%1,%2,%3}, [%4];"
                 : "=r"(r[0]), "=r"(r[1]), "=r"(r[2]), "=r"(r[3]) : "r"(addr) : "memory");
}
__device__ __forceinline__ void mmabf(float* c, const unsigned* a, const unsigned* b) {
    asm volatile("mma.sync.aligned.m16n8k16.row.col.f32.bf16.bf16.f32 "
                 "{%0,%1,%2,%3}, {%4,%5,%6,%7}, {%8,%9}, {%0,%1,%2,%3};"
                 : "+f"(c[0]), "+f"(c[1]), "+f"(c[2]), "+f"(c[3])
                 : "r"(a[0]), "r"(a[1]), "r"(a[2]), "r"(a[3]), "r"(b[0]), "r"(b[1]));
}
__device__ __forceinline__ unsigned packbf(float a, float b) {
    __nv_bfloat162 t = __floats2bfloat162_rn(a, b);
    return *(unsigned*)&t;
}

__global__ void zero_kernel(float* out, int n) {
    int i = blockIdx.x * blockDim.x + threadIdx.x;
    if (i < n) out[i] = 0.0f;
}

// g_B2[n][k]: k<256 = bf16_hi(W2cat[c][n]) (c=k, pad c>=224), k>=256 = bf16_lo
__global__ void prep_w2_kernel(const float* __restrict__ W2r, const float* __restrict__ W2s) {
    int i = blockIdx.x * blockDim.x + threadIdx.x;
    if (i >= 224 * 512) return;
    int n = i >> 9, k = i & 511;
    int seg = k >> 8, c = k & 255;
    float v = 0.f;
    if (c < 224) v = (c < 112) ? W2r[c * 224 + n] : W2s[(c - 112) * 224 + n];
    __nv_bfloat16 hv = __float2bfloat16(v);
    g_B2[i] = seg ? __float2bfloat16(v - __bfloat162float(hv)) : hv;
}

__global__ __launch_bounds__(224) void node_kernel(
    const float* __restrict__ x, const float* __restrict__ Wq,
    const float* __restrict__ Wk, const float* __restrict__ Wv, int N)
{
    __shared__ float xs[FDIM];
    const int c = threadIdx.x;
    const int h = c >> 5, i = c & 31;
    const int h2 = c / 56, i2 = c - h2 * 56;
    float4 wq[8], wk[8], wv[14];
    const float4* q4 = (const float4*)(Wq + (h * 32 + i) * 32);
    const float4* k4 = (const float4*)(Wk + (h * 32 + i) * 32);
    const float4* v4 = (const float4*)(Wv + (h2 * 56 + i2) * 56);
#pragma unroll
    for (int m = 0; m < 8; m++) { wq[m] = q4[m]; wk[m] = k4[m]; }
#pragma unroll
    for (int m = 0; m < 14; m++) wv[m] = v4[m];
    for (int n = blockIdx.x; n < N; n += gridDim.x) {
        __syncthreads();
        xs[c] = x[(size_t)n * FDIM + c];
        __syncthreads();
        float aq = 0.f, ak = 0.f, av = 0.f;
        const float4* xb = (const float4*)(xs + h * 32);
#pragma unroll
        for (int m = 0; m < 8; m++) {
            float4 xv = xb[m];
            aq += wq[m].x * xv.x + wq[m].y * xv.y + wq[m].z * xv.z + wq[m].w * xv.w;
            ak += wk[m].x * xv.x + wk[m].y * xv.y + wk[m].z * xv.z + wk[m].w * xv.w;
        }
        const float4* xb2 = (const float4*)(xs + h2 * 56);
#pragma unroll
        for (int m = 0; m < 14; m++) {
            float4 xv = xb2[m];
            av += wv[m].x * xv.x + wv[m].y * xv.y + wv[m].z * xv.z + wv[m].w * xv.w;
        }
        g_q[(size_t)n * FDIM + c] = silu_f(aq);
        g_k[(size_t)n * FDIM + c] = silu_f(ak);
        g_v[(size_t)n * FDIM + c] = av;
    }
}

__global__ __launch_bounds__(256, 1) void fused_edge_kernel(
    const float* __restrict__ rbf, const float* __restrict__ cut,
    const int* __restrict__ idx_i, const int* __restrict__ idx_j,
    const float* __restrict__ ev,
    const float* __restrict__ W1r, const float* __restrict__ b1r,
    const float* __restrict__ W1s, const float* __restrict__ b1s,
    const float* __restrict__ b2r, const float* __restrict__ b2s, int P)
{
    extern __shared__ char smc[];
    const unsigned sb = smem_u32(smc);
    const int t = threadIdx.x, w = t >> 5, L = t & 31;
    const int e0 = blockIdx.x * TE;
    const int rw = w * 16;

    float* cut_s = (float*)(smc + OFF_CUT);
    float* b2c_s = (float*)(smc + OFF_B2C);
    int*   ii_s  = (int*)(smc + OFF_II);
    int*   jj_s  = (int*)(smc + OFF_JJ);
    float* l0_s  = (float*)(smc + OFF_L0);

    // ---- stage misc + B1 (hi/lo) ----
    if (t < 224) b2c_s[t] = b2r[t] + b2s[t];
    if (t < TE) {
        int eg = min(e0 + t, P - 1);
        int a = idx_i[eg], b = idx_j[eg];
        ii_s[t] = a; jj_s[t] = b;
        cut_s[t] = (e0 + t < P) ? cut[e0 + t] : 0.f;
        float s0 = 0.f, s1 = 0.f, s2 = 0.f;
        const float* ea = ev + a * NORD;
        const float* eb = ev + b * NORD;
#pragma unroll
        for (int o = 0; o < NORD; o++) {
            float d = eb[o] - ea[o];
            float dd = d * d;
            if (o < 3) s0 += dd; else if (o < 8) s1 += dd; else s2 += dd;
        }
        l0_s[t] = s0; l0_s[128 + t] = s1; l0_s[256 + t] = s2;
    }
    for (int i = t; i < 224 * 48; i += 256) {
        int n = i / 48, k = i - n * 48;
        float v = 0.f;
        if (n < 112) {
            if (k < 32) v = W1r[k * 112 + n];
            else if (k == 35) v = b1r[n];
        } else {
            int n2 = n - 112;
            if (k >= 32 && k < 35) v = W1s[(k - 32) * 112 + n2];
            else if (k == 35) v = b1s[n2];
        }
        __nv_bfloat16 hv = __float2bfloat16(v);
        ((__nv_bfloat16*)(smc + OFF_B1H))[n * 56 + k] = hv;
        ((__nv_bfloat16*)(smc + OFF_B1L))[n * 56 + k] =
            __float2bfloat16(v - __bfloat162float(hv));
    }
    __syncthreads();

    // ---- stage A1 = [rbf*cut | l0 | 1 | 0] (hi/lo) ----
    for (int i = t; i < TE * 48; i += 256) {
        int e = i / 48, k = i - e * 48;
        float v = 0.f;
        if (k < 32)      v = ((e0 + e < P) ? rbf[(size_t)(e0 + e) * 32 + k] : 0.f) * cut_s[e];
        else if (k < 35) v = l0_s[(k - 32) * 128 + e];
        else if (k == 35) v = 1.f;
        __nv_bfloat16 hv = __float2bfloat16(v);
        ((__nv_bfloat16*)(smc + OFF_A1H))[e * 56 + k] = hv;
        ((__nv_bfloat16*)(smc + OFF_A1L))[e * 56 + k] =
            __float2bfloat16(v - __bfloat162float(hv));
    }
    __syncthreads();

    // ---- GEMM1: h[128][224] = A1 @ B1^T via mma.sync ----
    unsigned ah[3][4], al[3][4];
#pragma unroll
    for (int ks = 0; ks < 3; ks++) {
        unsigned row = rw + (L & 15), col = ks * 16 + (L >> 4) * 8;
        ldm4(ah[ks], sb + OFF_A1H + (row * 56 + col) * 2);
        ldm4(al[ks], sb + OFF_A1L + (row * 56 + col) * 2);
    }
    float c1[28][4];
#pragma unroll
    for (int j = 0; j < 28; j++)
#pragma unroll
        for (int q = 0; q < 4; q++) c1[j][q] = 0.f;
#pragma unroll
    for (int j = 0; j < 28; j++) {
        unsigned nrow = 8 * j + (L >> 2);
        unsigned base = nrow * 112 + 4 * (L & 3);
        unsigned bh[3][2], bl[3][2];
#pragma unroll
        for (int ks = 0; ks < 3; ks++) {
            bh[ks][0] = *(unsigned*)(smc + OFF_B1H + base + ks * 32);
            bh[ks][1] = *(unsigned*)(smc + OFF_B1H + base + ks * 32 + 16);
            bl[ks][0] = *(unsigned*)(smc + OFF_B1L + base + ks * 32);
            bl[ks][1] = *(unsigned*)(smc + OFF_B1L + base + ks * 32 + 16);
        }
#pragma unroll
        for (int ks = 0; ks < 3; ks++) {
            mmabf(c1[j], ah[ks], bh[ks]);
            mmabf(c1[j], al[ks], bh[ks]);
            mmabf(c1[j], ah[ks], bl[ks]);
        }
    }
    __syncthreads();   // B1/A1 reads done; regions reusable

    // ---- silu + split, write A2 (hi/lo); preload B2 panel 0 ----
    {
        int rA = rw + (L >> 2), rB = rA + 8;
#pragma unroll
        for (int j = 0; j < 28; j++) {
            int c0 = 8 * j + 2 * (L & 3);
            float v00 = silu_f(c1[j][0]), v01 = silu_f(c1[j][1]);
            float v10 = silu_f(c1[j][2]), v11 = silu_f(c1[j][3]);
            __nv_bfloat16 h00 = __float2bfloat16(v00), h01 = __float2bfloat16(v01);
            __nv_bfloat16 h10 = __float2bfloat16(v10), h11 = __float2bfloat16(v11);
            *(unsigned*)(smc + OFF_A2H + (rA * 232 + c0) * 2) =
                ((unsigned)*(unsigned short*)&h01 << 16) | *(unsigned short*)&h00;
            *(unsigned*)(smc + OFF_A2H + (rB * 232 + c0) * 2) =
                ((unsigned)*(unsigned short*)&h11 << 16) | *(unsigned short*)&h10;
            *(unsigned*)(smc + OFF_A2L + (rA * 232 + c0) * 2) =
                packbf(v00 - __bfloat162float(h00), v01 - __bfloat162float(h01));
            *(unsigned*)(smc + OFF_A2L + (rB * 232 + c0) * 2) =
                packbf(v10 - __bfloat162float(h10), v11 - __bfloat162float(h11));
        }
    }
    for (int i = t; i < 896; i += 256) {
        int hl = i >= 448, i2 = i - hl * 448;
        int n = i2 >> 1, half = i2 & 1;
        *(uint4*)(smc + OFF_PANEL + hl * 10752 + (n * 24 + half * 8) * 2) =
            *(const uint4*)(g_B2 + (size_t)n * 512 + hl * 256 + half * 8);
    }
    __syncthreads();

    // ---- GEMM2 mainloop: 14 k-panels, double-buffered ----
    float c2[28][4];
#pragma unroll
    for (int j = 0; j < 28; j++)
#pragma unroll
        for (int q = 0; q < 4; q++) c2[j][q] = 0.f;

    for (int ks = 0; ks < 14; ks++) {
        if (ks < 13) {
            char* dst = smc + OFF_PANEL + ((ks + 1) & 1) * PANEL_SZ;
            for (int i = t; i < 896; i += 256) {
                int hl = i >= 448, i2 = i - hl * 448;
                int n = i2 >> 1, half = i2 & 1;
                *(uint4*)(dst + hl * 10752 + (n * 24 + half * 8) * 2) =
                    *(const uint4*)(g_B2 + (size_t)n * 512 + hl * 256 + (ks + 1) * 16 + half * 8);
            }
        }
        unsigned Ah[4], Al[4];
        {
            unsigned row = rw + (L & 15), col = ks * 16 + (L >> 4) * 8;
            ldm4(Ah, sb + OFF_A2H + (row * 232 + col) * 2);
            ldm4(Al, sb + OFF_A2L + (row * 232 + col) * 2);
        }
        char* pc = smc + OFF_PANEL + (ks & 1) * PANEL_SZ;
        unsigned nbase = (L >> 2) * 48 + (L & 3) * 4;
#pragma unroll
        for (int j = 0; j < 28; j++) {
            unsigned ba = (unsigned)(8 * j) * 48 + nbase;
            unsigned bh[2], bl[2];
            bh[0] = *(unsigned*)(pc + ba);
            bh[1] = *(unsigned*)(pc + ba + 16);
            bl[0] = *(unsigned*)(pc + 10752 + ba);
            bl[1] = *(unsigned*)(pc + 10752 + ba + 16);
            mmabf(c2[j], Ah, bh);
            mmabf(c2[j], Al, bh);
            mmabf(c2[j], Ah, bl);
        }
        __syncthreads();
    }

    // ---- epilogue: qk staging then alpha ----
    float* qk_s = (float*)(smc + OFF_QK);
    for (int i = t; i < 128 * 56; i += 256) {
        int e = i / 56, c4 = (i - e * 56) * 4;
        float4 q4 = *(const float4*)(g_q + (size_t)ii_s[e] * FDIM + c4);
        float4 k4 = *(const float4*)(g_k + (size_t)jj_s[e] * FDIM + c4);
        float4 r;
        r.x = q4.x * k4.x; r.y = q4.y * k4.y; r.z = q4.z * k4.z; r.w = q4.w * k4.w;
        *(float4*)(qk_s + e * 228 + c4) = r;
    }
    __syncthreads();
    {
        int rA = rw + (L >> 2), rB = rA + 8;
        const float* qA = qk_s + rA * 228;
        const float* qB = qk_s + rB * 228;
#pragma unroll
        for (int h = 0; h < 7; h++) {
            float pA = 0.f, pB = 0.f;
#pragma unroll
            for (int jj = 0; jj < 4; jj++) {
                int j = 4 * h + jj;
                int c0 = 8 * j + 2 * (L & 3);
                float b0 = b2c_s[c0], b1v = b2c_s[c0 + 1];
                pA += qA[c0] * (c2[j][0] + b0) + qA[c0 + 1] * (c2[j][1] + b1v);
                pB += qB[c0] * (c2[j][2] + b0) + qB[c0 + 1] * (c2[j][3] + b1v);
            }
            pA += __shfl_xor_sync(0xffffffffu, pA, 1);
            pA += __shfl_xor_sync(0xffffffffu, pA, 2);
            pB += __shfl_xor_sync(0xffffffffu, pB, 1);
            pB += __shfl_xor_sync(0xffffffffu, pB, 2);
            if ((L & 3) == 0) {
                int eA = e0 + rA;
                if (eA < P) g_alpha[(size_t)eA * 8 + h] = pA * cut_s[rA];
                int eB = e0 + rB;
                if (eB < P) g_alpha[(size_t)eB * 8 + h] = pB * cut_s[rB];
            }
        }
    }
}

__global__ __launch_bounds__(256) void scatter_kernel(
    const float* __restrict__ ylm, const int* __restrict__ idx_i,
    const int* __restrict__ idx_j, float* __restrict__ outx,
    float* __restrict__ outev, int P)
{
    __shared__ float alp_s[7 * TE];
    __shared__ float ylm_s[TE * NORD];
    __shared__ int ii_s[TE], jj_s[TE];
    const int t = threadIdx.x;
    const int e0 = blockIdx.x * TE;
    const int nE = min(TE, P - e0);

    if (t < TE) {
        int eg = min(e0 + t, P - 1);
        ii_s[t] = idx_i[eg];
        jj_s[t] = idx_j[eg];
    }
    for (int i = t; i < 7 * TE; i += 256) {
        int h = i >> 7, e = i & 127;
        alp_s[i] = (e0 + e < P) ? g_alpha[(size_t)(e0 + e) * 8 + h] : 0.f;
    }
    for (int i = t; i < TE * NORD; i += 256)
        ylm_s[i] = (e0 + i / NORD < P) ? ylm[(size_t)e0 * NORD + i] : 0.f;
    __syncthreads();

    if (t < FDIM) {
        int hc = t / 56;
        const float* arow = alp_s + hc * TE;
        int icur = ii_s[0];
        float a2 = 0.f;
        for (int e = 0; e < nE; e++) {
            int ie = ii_s[e];
            if (ie != icur) {
                atomicAdd(outx + (size_t)icur * FDIM + t, a2);
                a2 = 0.f; icur = ie;
            }
            a2 += arow[e] * g_v[(size_t)jj_s[e] * FDIM + t];
        }
        atomicAdd(outx + (size_t)icur * FDIM + t, a2);
    } else if (t < FDIM + NORD) {
        int o = t - FDIM;
        int hd = (o < 3) ? 4 : (o < 8) ? 5 : 6;
        const float* arow = alp_s + hd * TE;
        int icur = ii_s[0];
        float a2 = 0.f;
        for (int e = 0; e < nE; e++) {
            int ie = ii_s[e];
            if (ie != icur) {
                atomicAdd(outev + (size_t)icur * NORD + o, a2);
                a2 = 0.f; icur = ie;
            }
            a2 += arow[e] * ylm_s[e * NORD + o];
        }
        atomicAdd(outev + (size_t)icur * NORD + o, a2);
    }
}

extern "C" void kernel_launch(void* const* d_in, const int* in_sizes, int n_in,
                              void* d_out, int out_size)
{
    const float* x    = (const float*)d_in[0];
    const float* ev   = (const float*)d_in[1];
    const float* rbf  = (const float*)d_in[2];
    const float* ylm  = (const float*)d_in[3];
    const float* cutp = (const float*)d_in[4];
    const int*   idxi = (const int*)d_in[5];
    const int*   idxj = (const int*)d_in[6];
    const float* W1r  = (const float*)d_in[7];
    const float* b1r  = (const float*)d_in[8];
    const float* W2r  = (const float*)d_in[9];
    const float* b2r  = (const float*)d_in[10];
    const float* W1s  = (const float*)d_in[11];
    const float* b1s  = (const float*)d_in[12];
    const float* W2s  = (const float*)d_in[13];
    const float* b2s  = (const float*)d_in[14];
    const float* Wq   = (const float*)d_in[15];
    const float* Wk   = (const float*)d_in[16];
    const float* Wv   = (const float*)d_in[17];

    int N = in_sizes[0] / FDIM;
    int P = in_sizes[4];
    float* out   = (float*)d_out;
    float* outx  = out;
    float* outev = out + (size_t)N * FDIM;

    zero_kernel<<<(out_size + 255) / 256, 256>>>(out, out_size);
    prep_w2_kernel<<<(224 * 512 + 255) / 256, 256>>>(W2r, W2s);
    node_kernel<<<1024, 224>>>(x, Wq, Wk, Wv, N);

    cudaFuncSetAttribute(fused_edge_kernel,
                         cudaFuncAttributeMaxDynamicSharedMemorySize, SM_TOTAL);
    int nb = (P + TE - 1) / TE;
    fused_edge_kernel<<<nb, 256, SM_TOTAL>>>(rbf, cutp, idxi, idxj, ev,
                                             W1r, b1r, W1s, b1s, b2r, b2s, P);
    scatter_kernel<<<nb, 256>>>(ylm, idxi, idxj, outx, outev, P);
}